// round 1
// baseline (speedup 1.0000x reference)
#include <cuda_runtime.h>
#include <math.h>

#define BB 2
#define TT 512
#define CC 128
#define HH 512
#define ROWS (BB*TT)   // 1024

// ---------------- scratch (no allocations allowed) ----------------
__device__ float g_h  [ROWS*CC];
__device__ float g_hs [ROWS*CC];
__device__ float g_r  [ROWS*CC];
__device__ float g_k  [ROWS*CC];
__device__ float g_v  [ROWS*CC];
__device__ float g_wk [ROWS*CC];
__device__ float g_y  [ROWS*CC];
__device__ float g_h2 [ROWS*CC];
__device__ float g_mid[ROWS*HH];

// ---------------- LayerNorm: one block per row, 128 threads ----------------
__global__ void ln_kernel(const float* __restrict__ in, const float* __restrict__ gam,
                          const float* __restrict__ bet, float* __restrict__ out) {
    int row = blockIdx.x;
    int c   = threadIdx.x;
    float x = in[row*CC + c];
    int lane = c & 31, w = c >> 5;
    __shared__ float sm[4];
    float s = x;
    #pragma unroll
    for (int o = 16; o; o >>= 1) s += __shfl_xor_sync(0xffffffffu, s, o);
    if (lane == 0) sm[w] = s;
    __syncthreads();
    float mean = (sm[0]+sm[1]+sm[2]+sm[3]) * (1.0f/CC);
    __syncthreads();
    float d = x - mean;
    float s2 = d*d;
    #pragma unroll
    for (int o = 16; o; o >>= 1) s2 += __shfl_xor_sync(0xffffffffu, s2, o);
    if (lane == 0) sm[w] = s2;
    __syncthreads();
    float var = (sm[0]+sm[1]+sm[2]+sm[3]) * (1.0f/CC);
    out[row*CC + c] = d * rsqrtf(var + 1e-5f) * gam[c] + bet[c];
}

// ---------------- TemporalShift: hs = h + mu * shifted(h) ----------------
__global__ void shift_kernel(const float* __restrict__ h, const float* __restrict__ mu,
                             float* __restrict__ hs) {
    int i = blockIdx.x*blockDim.x + threadIdx.x;
    if (i >= ROWS*CC) return;
    int c = i & (CC-1);
    int t = (i >> 7) & (TT-1);
    float sh = 0.0f;
    if (c < CC/2) { if (t > 0)     sh = h[i - CC]; }   // past half shifted right
    else          { if (t < TT-1)  sh = h[i + CC]; }   // future half shifted left
    hs[i] = h[i] + mu[c]*sh;
}

// ---------------- fp32 GEMM: out = epilogue(A[M,K] @ W[K,N] + bias) ----------------
// MODE: 0 none, 1 sigmoid, 2 exact gelu, 3 add residual
template<int MODE>
__global__ void gemm_kernel(const float* __restrict__ A, const float* __restrict__ W,
                            const float* __restrict__ bias, const float* __restrict__ res,
                            float* __restrict__ out, int M, int N, int K) {
    __shared__ float As[16][64];   // transposed: As[k][m]
    __shared__ float Bs[16][64];   // Bs[k][n]
    int bm = blockIdx.y*64, bn = blockIdx.x*64;
    int tid = threadIdx.x;               // 256 threads
    int aRow = tid >> 2,  aK = (tid & 3)  << 2;
    int bK   = tid >> 4,  bN = (tid & 15) << 2;
    int ty   = tid >> 4,  tx = tid & 15;
    float acc[4][4] = {};
    for (int k0 = 0; k0 < K; k0 += 16) {
        float4 av = *(const float4*)(A + (size_t)(bm+aRow)*K + k0 + aK);
        As[aK+0][aRow] = av.x; As[aK+1][aRow] = av.y;
        As[aK+2][aRow] = av.z; As[aK+3][aRow] = av.w;
        float4 bv = *(const float4*)(W + (size_t)(k0+bK)*N + bn + bN);
        *(float4*)&Bs[bK][bN] = bv;
        __syncthreads();
        #pragma unroll
        for (int kk = 0; kk < 16; kk++) {
            float4 a = *(float4*)&As[kk][ty<<2];
            float4 b = *(float4*)&Bs[kk][tx<<2];
            float aa[4] = {a.x,a.y,a.z,a.w};
            float bb[4] = {b.x,b.y,b.z,b.w};
            #pragma unroll
            for (int i = 0; i < 4; i++)
                #pragma unroll
                for (int j = 0; j < 4; j++)
                    acc[i][j] = fmaf(aa[i], bb[j], acc[i][j]);
        }
        __syncthreads();
    }
    #pragma unroll
    for (int i = 0; i < 4; i++) {
        int m = bm + (ty<<2) + i;
        #pragma unroll
        for (int j = 0; j < 4; j++) {
            int n = bn + (tx<<2) + j;
            float x = acc[i][j] + bias[n];
            if (MODE == 1) x = 1.0f / (1.0f + expf(-x));
            if (MODE == 2) x = 0.5f * x * (1.0f + erff(x * 0.70710678118654752f));
            if (MODE == 3) x += res[(size_t)m*N + n];
            out[(size_t)m*N + n] = x;
        }
    }
}

// ---------------- WKV: wk = r * x_f   (x_b == x_f, see derivation) ----------------
// Block = 256 threads = 8 warps = 4 rows x 2 l-segments (256 l each).
// Per warp: lane owns 4 channels; E_c(l) = exp(s_l * b_c) via multiplicative
// recurrence (s_l uniform grid), per-l softmax denominator via warp shuffle.
__global__ void wkv_kernel(const float* __restrict__ k, const float* __restrict__ v,
                           const float* __restrict__ r, const float* __restrict__ wd,
                           float* __restrict__ wk) {
    const int warp = threadIdx.x >> 5, lane = threadIdx.x & 31;
    const int rloc = warp >> 1, seg = warp & 1;
    const int row  = blockIdx.x*4 + rloc;
    const int b    = row >> 9;           // T = 512
    const int c0   = lane << 2;
    __shared__ float s_acc[4][CC];

    float4 k4 = *(const float4*)(k  + row*CC + c0);
    float4 w4 = *(const float4*)(wd + c0);
    float a0 = k4.x * (-expf(w4.x));
    float a1 = k4.y * (-expf(w4.y));
    float a2 = k4.z * (-expf(w4.z));
    float a3 = k4.w * (-expf(w4.w));
    float amax = fmaxf(fmaxf(a0,a1), fmaxf(a2,a3));
    #pragma unroll
    for (int o = 16; o; o >>= 1) amax = fmaxf(amax, __shfl_xor_sync(0xffffffffu, amax, o));
    float b0 = a0 - amax, b1 = a1 - amax, b2 = a2 - amax, b3 = a3 - amax;

    const float inv511 = 1.0f/511.0f;
    const int l0 = seg * 256;
    const float sstart = (float)(511 - l0) * inv511;   // s at first l of this segment
    float E0 = expf(b0*sstart), E1 = expf(b1*sstart);
    float E2 = expf(b2*sstart), E3 = expf(b3*sstart);
    // per-step factor: s decreases by 1/511 as l increments
    float g0 = expf(-b0*inv511), g1 = expf(-b1*inv511);
    float g2 = expf(-b2*inv511), g3 = expf(-b3*inv511);

    float acc0 = 0.f, acc1 = 0.f, acc2 = 0.f, acc3 = 0.f;
    const float* vbase = v + ((size_t)(b << 9))*CC + c0;

    #pragma unroll 4
    for (int l = l0; l < l0 + 256; ++l) {
        float z = (E0 + E1) + (E2 + E3);
        #pragma unroll
        for (int o = 16; o; o >>= 1) z += __shfl_xor_sync(0xffffffffu, z, o);
        float inv = __fdividef(1.0f, z + 1e-6f);
        float4 vv = *(const float4*)(vbase + (size_t)l*CC);
        acc0 = fmaf(E0*inv, vv.x, acc0);
        acc1 = fmaf(E1*inv, vv.y, acc1);
        acc2 = fmaf(E2*inv, vv.z, acc2);
        acc3 = fmaf(E3*inv, vv.w, acc3);
        E0 *= g0; E1 *= g1; E2 *= g2; E3 *= g3;
    }

    if (seg == 0) {
        s_acc[rloc][c0+0] = acc0; s_acc[rloc][c0+1] = acc1;
        s_acc[rloc][c0+2] = acc2; s_acc[rloc][c0+3] = acc3;
    }
    __syncthreads();
    if (seg == 1) {
        float4 r4 = *(const float4*)(r + row*CC + c0);
        float* o = wk + row*CC + c0;
        // wk = r * (x_f + x_b) * 0.5 = r * x_f  (identity: x_b == x_f)
        o[0] = r4.x * (acc0 + s_acc[rloc][c0+0]);
        o[1] = r4.y * (acc1 + s_acc[rloc][c0+1]);
        o[2] = r4.z * (acc2 + s_acc[rloc][c0+2]);
        o[3] = r4.w * (acc3 + s_acc[rloc][c0+3]);
    }
}

// ---------------- launch ----------------
extern "C" void kernel_launch(void* const* d_in, const int* in_sizes, int n_in,
                              void* d_out, int out_size) {
    const float* x       = (const float*)d_in[0];
    const float* ln1_g   = (const float*)d_in[1];
    const float* ln1_b   = (const float*)d_in[2];
    const float* mu      = (const float*)d_in[3];
    const float* Wr      = (const float*)d_in[4];
    const float* br      = (const float*)d_in[5];
    const float* Wk      = (const float*)d_in[6];
    const float* bk      = (const float*)d_in[7];
    const float* Wv      = (const float*)d_in[8];
    const float* bv      = (const float*)d_in[9];
    const float* w_decay = (const float*)d_in[10];
    const float* Wo      = (const float*)d_in[11];
    const float* bo      = (const float*)d_in[12];
    const float* ln2_g   = (const float*)d_in[13];
    const float* ln2_b   = (const float*)d_in[14];
    const float* W1      = (const float*)d_in[15];
    const float* b1      = (const float*)d_in[16];
    const float* W2      = (const float*)d_in[17];
    const float* b2      = (const float*)d_in[18];
    float* out = (float*)d_out;

    float *h, *hs, *r_, *k_, *v_, *wkp, *y, *h2, *mid;
    cudaGetSymbolAddress((void**)&h,   g_h);
    cudaGetSymbolAddress((void**)&hs,  g_hs);
    cudaGetSymbolAddress((void**)&r_,  g_r);
    cudaGetSymbolAddress((void**)&k_,  g_k);
    cudaGetSymbolAddress((void**)&v_,  g_v);
    cudaGetSymbolAddress((void**)&wkp, g_wk);
    cudaGetSymbolAddress((void**)&y,   g_y);
    cudaGetSymbolAddress((void**)&h2,  g_h2);
    cudaGetSymbolAddress((void**)&mid, g_mid);

    ln_kernel<<<ROWS, CC>>>(x, ln1_g, ln1_b, h);
    shift_kernel<<<(ROWS*CC)/256, 256>>>(h, mu, hs);

    gemm_kernel<1><<<dim3(CC/64, ROWS/64), 256>>>(hs, Wr, br, nullptr, r_, ROWS, CC, CC);
    gemm_kernel<0><<<dim3(CC/64, ROWS/64), 256>>>(hs, Wk, bk, nullptr, k_, ROWS, CC, CC);
    gemm_kernel<0><<<dim3(CC/64, ROWS/64), 256>>>(hs, Wv, bv, nullptr, v_, ROWS, CC, CC);

    wkv_kernel<<<ROWS/4, 256>>>(k_, v_, r_, w_decay, wkp);

    gemm_kernel<3><<<dim3(CC/64, ROWS/64), 256>>>(wkp, Wo, bo, x, y, ROWS, CC, CC);
    ln_kernel<<<ROWS, CC>>>(y, ln2_g, ln2_b, h2);
    gemm_kernel<2><<<dim3(HH/64, ROWS/64), 256>>>(h2, W1, b1, nullptr, mid, ROWS, HH, CC);
    gemm_kernel<3><<<dim3(CC/64, ROWS/64), 256>>>(mid, W2, b2, y, out, ROWS, CC, HH);
}

// round 2
// speedup vs baseline: 1.5021x; 1.5021x over previous
#include <cuda_runtime.h>
#include <math.h>

#define TT 512
#define CC 128
#define HH 512
#define ROWS 1024   // B*T

// ---------------- scratch ----------------
__device__ float g_hs [ROWS*CC];
__device__ float g_r  [ROWS*CC];
__device__ float g_k  [ROWS*CC];
__device__ float g_v  [ROWS*CC];
__device__ float g_wk [ROWS*CC];
__device__ float g_y  [ROWS*CC];
__device__ float g_h2 [ROWS*CC];
__device__ float g_mid[ROWS*HH];

// ---------------- helpers ----------------
__device__ __forceinline__ float wsum(float x) {
    #pragma unroll
    for (int o = 16; o; o >>= 1) x += __shfl_xor_sync(0xffffffffu, x, o);
    return x;
}
__device__ __forceinline__ float wmax(float x) {
    #pragma unroll
    for (int o = 16; o; o >>= 1) x = fmaxf(x, __shfl_xor_sync(0xffffffffu, x, o));
    return x;
}
__device__ __forceinline__ float rcpa(float x) {
    float r; asm("rcp.approx.f32 %0, %1;" : "=f"(r) : "f"(x)); return r;
}

// ---------------- fused LN1 + TemporalShift ----------------
// Block = 16 t-rows of one batch + 1-row halo each side. 256 threads, grid 64.
__global__ void ln_shift_kernel(const float* __restrict__ x,
                                const float* __restrict__ gam, const float* __restrict__ bet,
                                const float* __restrict__ mu, float* __restrict__ hs) {
    __shared__ float sh[18][CC];
    const int tid = threadIdx.x;
    const int w = tid >> 5, lane = tid & 31;
    const int b  = blockIdx.x >> 5;
    const int t0 = (blockIdx.x & 31) << 4;

    float4 g4 = *(const float4*)(gam + (lane << 2));
    float4 b4 = *(const float4*)(bet + (lane << 2));

    for (int hr = w; hr < 18; hr += 8) {
        int t = t0 - 1 + hr;
        bool ok = (t >= 0) && (t < TT);
        float4 xv = make_float4(0.f, 0.f, 0.f, 0.f);
        if (ok) xv = *(const float4*)(x + (size_t)((b << 9) + t)*CC + (lane << 2));
        float s = (xv.x + xv.y) + (xv.z + xv.w);
        float mean = wsum(s) * (1.0f/CC);
        float d0 = xv.x - mean, d1 = xv.y - mean, d2 = xv.z - mean, d3 = xv.w - mean;
        float ss = (d0*d0 + d1*d1) + (d2*d2 + d3*d3);
        float rs = rsqrtf(wsum(ss) * (1.0f/CC) + 1e-5f);
        int c = lane << 2;
        sh[hr][c+0] = ok ? d0*rs*g4.x + b4.x : 0.f;
        sh[hr][c+1] = ok ? d1*rs*g4.y + b4.y : 0.f;
        sh[hr][c+2] = ok ? d2*rs*g4.z + b4.z : 0.f;
        sh[hr][c+3] = ok ? d3*rs*g4.w + b4.w : 0.f;
    }
    __syncthreads();
    for (int i = tid; i < 16*CC; i += 256) {
        int rl = i >> 7, c = i & (CC-1);
        float val = sh[rl+1][c];
        float shv = (c < CC/2) ? sh[rl][c] : sh[rl+2][c];
        hs[(size_t)((b << 9) + t0 + rl)*CC + c] = val + mu[c]*shv;
    }
}

// ---------------- GEMM mainloop: 16-row x 128-col tile, 256 threads ----------------
// A[M,K] (row stride lda) @ W[K,128] (row stride ldw). Warp w owns output rows 2w,2w+1;
// lane owns 4 cols. Result in acc[2][4].
__device__ __forceinline__ void gemm_tile(const float* __restrict__ A, int lda,
                                          const float* __restrict__ W, int ldw,
                                          int K, float (&acc)[2][4]) {
    __shared__ float As[16][17];
    __shared__ float Bs[16][CC];
    const int tid  = threadIdx.x;
    const int bm   = blockIdx.y << 4;
    const int arow = tid >> 4, ak = tid & 15;
    const int w = tid >> 5, lane = tid & 31;
    const int bk = tid >> 5, bn4 = tid & 31;

    for (int k0 = 0; k0 < K; k0 += 16) {
        As[ak][arow] = A[(size_t)(bm + arow)*lda + k0 + ak];
        *(float4*)&Bs[bk  ][bn4 << 2] = *(const float4*)(W + (size_t)(k0 + bk    )*ldw + (bn4 << 2));
        *(float4*)&Bs[bk+8][bn4 << 2] = *(const float4*)(W + (size_t)(k0 + bk + 8)*ldw + (bn4 << 2));
        __syncthreads();
        #pragma unroll
        for (int kk = 0; kk < 16; kk++) {
            float a0 = As[kk][(w << 1)];
            float a1 = As[kk][(w << 1) + 1];
            float4 bv = *(float4*)&Bs[kk][lane << 2];
            acc[0][0] = fmaf(a0, bv.x, acc[0][0]);
            acc[0][1] = fmaf(a0, bv.y, acc[0][1]);
            acc[0][2] = fmaf(a0, bv.z, acc[0][2]);
            acc[0][3] = fmaf(a0, bv.w, acc[0][3]);
            acc[1][0] = fmaf(a1, bv.x, acc[1][0]);
            acc[1][1] = fmaf(a1, bv.y, acc[1][1]);
            acc[1][2] = fmaf(a1, bv.z, acc[1][2]);
            acc[1][3] = fmaf(a1, bv.w, acc[1][3]);
        }
        __syncthreads();
    }
}

// ---------------- fused r/k/v GEMMs (gridDim.z selects matrix) ----------------
__global__ void rkv_kernel(const float* __restrict__ hs,
                           const float* __restrict__ Wr, const float* __restrict__ br,
                           const float* __restrict__ Wk, const float* __restrict__ bk,
                           const float* __restrict__ Wv, const float* __restrict__ bv,
                           float* __restrict__ ro, float* __restrict__ ko, float* __restrict__ vo) {
    const int z = blockIdx.z;
    const float* W  = (z == 0) ? Wr : (z == 1) ? Wk : Wv;
    const float* bb = (z == 0) ? br : (z == 1) ? bk : bv;
    float* o        = (z == 0) ? ro : (z == 1) ? ko : vo;
    float acc[2][4] = {};
    gemm_tile(hs, CC, W, CC, CC, acc);
    const int w = threadIdx.x >> 5, lane = threadIdx.x & 31, bm = blockIdx.y << 4;
    float4 bias4 = *(const float4*)(bb + (lane << 2));
    #pragma unroll
    for (int i = 0; i < 2; i++) {
        int m = bm + (w << 1) + i;
        float v0 = acc[i][0] + bias4.x, v1 = acc[i][1] + bias4.y;
        float v2 = acc[i][2] + bias4.z, v3 = acc[i][3] + bias4.w;
        if (z == 0) {
            v0 = 1.0f/(1.0f + expf(-v0)); v1 = 1.0f/(1.0f + expf(-v1));
            v2 = 1.0f/(1.0f + expf(-v2)); v3 = 1.0f/(1.0f + expf(-v3));
        }
        *(float4*)(o + (size_t)m*CC + (lane << 2)) = make_float4(v0, v1, v2, v3);
    }
}

// ---------------- WKV: wk = r * x_f (x_b == x_f identity) ----------------
// 1024 threads = 32 warps = 8 rows x 4 l-segments (128 l each). Grid 128.
__global__ void __launch_bounds__(1024, 1)
wkv_kernel(const float* __restrict__ k, const float* __restrict__ v,
           const float* __restrict__ r, const float* __restrict__ wd,
           float* __restrict__ wk) {
    __shared__ float s_acc[4][8][CC];
    const int tid = threadIdx.x;
    const int wid = tid >> 5, lane = tid & 31;
    const int rloc = wid >> 2, seg = wid & 3;
    const int row  = (blockIdx.x << 3) + rloc;
    const int b    = row >> 9;
    const int c0   = lane << 2;

    float4 k4 = *(const float4*)(k  + (size_t)row*CC + c0);
    float4 w4 = *(const float4*)(wd + c0);
    float a0 = k4.x * (-expf(w4.x));
    float a1 = k4.y * (-expf(w4.y));
    float a2 = k4.z * (-expf(w4.z));
    float a3 = k4.w * (-expf(w4.w));
    float amax = wmax(fmaxf(fmaxf(a0, a1), fmaxf(a2, a3)));
    float b0 = a0 - amax, b1 = a1 - amax, b2 = a2 - amax, b3 = a3 - amax;

    const float inv511 = 1.0f/511.0f;
    const int l0 = seg << 7;
    const float sstart = (float)(511 - l0) * inv511;
    float E0 = expf(b0*sstart), E1 = expf(b1*sstart);
    float E2 = expf(b2*sstart), E3 = expf(b3*sstart);
    float g0 = expf(-b0*inv511), g1 = expf(-b1*inv511);
    float g2 = expf(-b2*inv511), g3 = expf(-b3*inv511);

    float acc0 = 0.f, acc1 = 0.f, acc2 = 0.f, acc3 = 0.f;
    const float* vbase = v + ((size_t)(b << 9))*CC + c0;

    #pragma unroll 4
    for (int l = l0; l < l0 + 128; ++l) {
        float z = wsum((E0 + E1) + (E2 + E3));
        float inv = rcpa(z + 1e-6f);
        float4 vv = *(const float4*)(vbase + (size_t)l*CC);
        acc0 = fmaf(E0*inv, vv.x, acc0);
        acc1 = fmaf(E1*inv, vv.y, acc1);
        acc2 = fmaf(E2*inv, vv.z, acc2);
        acc3 = fmaf(E3*inv, vv.w, acc3);
        E0 *= g0; E1 *= g1; E2 *= g2; E3 *= g3;
    }

    s_acc[seg][rloc][c0+0] = acc0;
    s_acc[seg][rloc][c0+1] = acc1;
    s_acc[seg][rloc][c0+2] = acc2;
    s_acc[seg][rloc][c0+3] = acc3;
    __syncthreads();

    // finalize: 8 rows x 128 c = 1024 values, one per thread
    const int rl = tid >> 7, c = tid & (CC-1);
    float sum = (s_acc[0][rl][c] + s_acc[1][rl][c]) + (s_acc[2][rl][c] + s_acc[3][rl][c]);
    const int grow = (blockIdx.x << 3) + rl;
    wk[(size_t)grow*CC + c] = r[(size_t)grow*CC + c] * sum;
}

// ---------------- Wo GEMM + residual + LN2 (fused) ----------------
__global__ void wo_ln_kernel(const float* __restrict__ wkin, const float* __restrict__ Wo,
                             const float* __restrict__ bo, const float* __restrict__ x,
                             const float* __restrict__ g2, const float* __restrict__ be2,
                             float* __restrict__ y, float* __restrict__ h2) {
    float acc[2][4] = {};
    gemm_tile(wkin, CC, Wo, CC, CC, acc);
    const int w = threadIdx.x >> 5, lane = threadIdx.x & 31, bm = blockIdx.y << 4;
    float4 bias4 = *(const float4*)(bo  + (lane << 2));
    float4 g4    = *(const float4*)(g2  + (lane << 2));
    float4 b4    = *(const float4*)(be2 + (lane << 2));
    #pragma unroll
    for (int i = 0; i < 2; i++) {
        int m = bm + (w << 1) + i;
        float4 xv = *(const float4*)(x + (size_t)m*CC + (lane << 2));
        float y0 = acc[i][0] + bias4.x + xv.x;
        float y1 = acc[i][1] + bias4.y + xv.y;
        float y2 = acc[i][2] + bias4.z + xv.z;
        float y3 = acc[i][3] + bias4.w + xv.w;
        *(float4*)(y + (size_t)m*CC + (lane << 2)) = make_float4(y0, y1, y2, y3);
        float mean = wsum((y0 + y1) + (y2 + y3)) * (1.0f/CC);
        float d0 = y0 - mean, d1 = y1 - mean, d2 = y2 - mean, d3 = y3 - mean;
        float rs = rsqrtf(wsum((d0*d0 + d1*d1) + (d2*d2 + d3*d3)) * (1.0f/CC) + 1e-5f);
        *(float4*)(h2 + (size_t)m*CC + (lane << 2)) =
            make_float4(d0*rs*g4.x + b4.x, d1*rs*g4.y + b4.y,
                        d2*rs*g4.z + b4.z, d3*rs*g4.w + b4.w);
    }
}

// ---------------- W1 GEMM + exact gelu ----------------
__global__ void w1_kernel(const float* __restrict__ h2, const float* __restrict__ W1,
                          const float* __restrict__ b1, float* __restrict__ mid) {
    const int bn = blockIdx.x << 7;
    float acc[2][4] = {};
    gemm_tile(h2, CC, W1 + bn, HH, CC, acc);
    const int w = threadIdx.x >> 5, lane = threadIdx.x & 31, bm = blockIdx.y << 4;
    float4 bias4 = *(const float4*)(b1 + bn + (lane << 2));
    #pragma unroll
    for (int i = 0; i < 2; i++) {
        int m = bm + (w << 1) + i;
        float v0 = acc[i][0] + bias4.x, v1 = acc[i][1] + bias4.y;
        float v2 = acc[i][2] + bias4.z, v3 = acc[i][3] + bias4.w;
        const float s = 0.70710678118654752f;
        v0 = 0.5f*v0*(1.0f + erff(v0*s));
        v1 = 0.5f*v1*(1.0f + erff(v1*s));
        v2 = 0.5f*v2*(1.0f + erff(v2*s));
        v3 = 0.5f*v3*(1.0f + erff(v3*s));
        *(float4*)(mid + (size_t)m*HH + bn + (lane << 2)) = make_float4(v0, v1, v2, v3);
    }
}

// ---------------- W2 GEMM + residual -> out ----------------
__global__ void w2_kernel(const float* __restrict__ mid, const float* __restrict__ W2,
                          const float* __restrict__ b2, const float* __restrict__ y,
                          float* __restrict__ out) {
    float acc[2][4] = {};
    gemm_tile(mid, HH, W2, CC, HH, acc);
    const int w = threadIdx.x >> 5, lane = threadIdx.x & 31, bm = blockIdx.y << 4;
    float4 bias4 = *(const float4*)(b2 + (lane << 2));
    #pragma unroll
    for (int i = 0; i < 2; i++) {
        int m = bm + (w << 1) + i;
        float4 yv = *(const float4*)(y + (size_t)m*CC + (lane << 2));
        *(float4*)(out + (size_t)m*CC + (lane << 2)) =
            make_float4(acc[i][0] + bias4.x + yv.x, acc[i][1] + bias4.y + yv.y,
                        acc[i][2] + bias4.z + yv.z, acc[i][3] + bias4.w + yv.w);
    }
}

// ---------------- launch ----------------
extern "C" void kernel_launch(void* const* d_in, const int* in_sizes, int n_in,
                              void* d_out, int out_size) {
    const float* x       = (const float*)d_in[0];
    const float* ln1_g   = (const float*)d_in[1];
    const float* ln1_b   = (const float*)d_in[2];
    const float* mu      = (const float*)d_in[3];
    const float* Wr      = (const float*)d_in[4];
    const float* br      = (const float*)d_in[5];
    const float* Wk      = (const float*)d_in[6];
    const float* bk      = (const float*)d_in[7];
    const float* Wv      = (const float*)d_in[8];
    const float* bv      = (const float*)d_in[9];
    const float* w_decay = (const float*)d_in[10];
    const float* Wo      = (const float*)d_in[11];
    const float* bo      = (const float*)d_in[12];
    const float* ln2_g   = (const float*)d_in[13];
    const float* ln2_b   = (const float*)d_in[14];
    const float* W1      = (const float*)d_in[15];
    const float* b1      = (const float*)d_in[16];
    const float* W2      = (const float*)d_in[17];
    const float* b2      = (const float*)d_in[18];
    float* out = (float*)d_out;

    float *hs, *r_, *k_, *v_, *wkp, *y, *h2, *mid;
    cudaGetSymbolAddress((void**)&hs,  g_hs);
    cudaGetSymbolAddress((void**)&r_,  g_r);
    cudaGetSymbolAddress((void**)&k_,  g_k);
    cudaGetSymbolAddress((void**)&v_,  g_v);
    cudaGetSymbolAddress((void**)&wkp, g_wk);
    cudaGetSymbolAddress((void**)&y,   g_y);
    cudaGetSymbolAddress((void**)&h2,  g_h2);
    cudaGetSymbolAddress((void**)&mid, g_mid);

    ln_shift_kernel<<<64, 256>>>(x, ln1_g, ln1_b, mu, hs);
    rkv_kernel<<<dim3(1, 64, 3), 256>>>(hs, Wr, br, Wk, bk, Wv, bv, r_, k_, v_);
    wkv_kernel<<<128, 1024>>>(k_, v_, r_, w_decay, wkp);
    wo_ln_kernel<<<dim3(1, 64), 256>>>(wkp, Wo, bo, x, ln2_g, ln2_b, y, h2);
    w1_kernel<<<dim3(4, 64), 256>>>(h2, W1, b1, mid);
    w2_kernel<<<dim3(1, 64), 256>>>(mid, W2, b2, y, out);
}

// round 3
// speedup vs baseline: 1.5049x; 1.0019x over previous
#include <cuda_runtime.h>
#include <math.h>

#define TT 512
#define CC 128
#define HH 512
#define ROWS 1024   // B*T

// ---------------- scratch ----------------
__device__ float g_hs [ROWS*CC];
__device__ float g_r  [ROWS*CC];
__device__ float g_k  [ROWS*CC];
__device__ float g_v  [ROWS*CC];
__device__ float g_wk [ROWS*CC];
__device__ float g_y  [ROWS*CC];
__device__ float g_h2 [ROWS*CC];
__device__ float g_mid[ROWS*HH];

// ---------------- helpers ----------------
__device__ __forceinline__ float wsum(float x) {
    #pragma unroll
    for (int o = 16; o; o >>= 1) x += __shfl_xor_sync(0xffffffffu, x, o);
    return x;
}
__device__ __forceinline__ float wmax(float x) {
    #pragma unroll
    for (int o = 16; o; o >>= 1) x = fmaxf(x, __shfl_xor_sync(0xffffffffu, x, o));
    return x;
}
__device__ __forceinline__ float rcpa(float x) {
    float r; asm("rcp.approx.f32 %0, %1;" : "=f"(r) : "f"(x)); return r;
}

// ---------------- fused LN1 + TemporalShift: 8 rows/block, grid 128 ----------------
__global__ void __launch_bounds__(256)
ln_shift_kernel(const float* __restrict__ x,
                const float* __restrict__ gam, const float* __restrict__ bet,
                const float* __restrict__ mu, float* __restrict__ hs) {
    __shared__ float sh[10][CC];
    const int tid = threadIdx.x;
    const int w = tid >> 5, lane = tid & 31;
    const int b  = blockIdx.x >> 6;
    const int t0 = (blockIdx.x & 63) << 3;

    float4 g4 = *(const float4*)(gam + (lane << 2));
    float4 b4 = *(const float4*)(bet + (lane << 2));

    for (int hr = w; hr < 10; hr += 8) {
        int t = t0 - 1 + hr;
        bool ok = (t >= 0) && (t < TT);
        float4 xv = make_float4(0.f, 0.f, 0.f, 0.f);
        if (ok) xv = *(const float4*)(x + (size_t)((b << 9) + t)*CC + (lane << 2));
        float mean = wsum((xv.x + xv.y) + (xv.z + xv.w)) * (1.0f/CC);
        float d0 = xv.x - mean, d1 = xv.y - mean, d2 = xv.z - mean, d3 = xv.w - mean;
        float rs = rsqrtf(wsum((d0*d0 + d1*d1) + (d2*d2 + d3*d3)) * (1.0f/CC) + 1e-5f);
        int c = lane << 2;
        sh[hr][c+0] = ok ? d0*rs*g4.x + b4.x : 0.f;
        sh[hr][c+1] = ok ? d1*rs*g4.y + b4.y : 0.f;
        sh[hr][c+2] = ok ? d2*rs*g4.z + b4.z : 0.f;
        sh[hr][c+3] = ok ? d3*rs*g4.w + b4.w : 0.f;
    }
    __syncthreads();
    for (int i = tid; i < 8*CC; i += 256) {
        int rl = i >> 7, c = i & (CC-1);
        float val = sh[rl+1][c];
        float shv = (c < CC/2) ? sh[rl][c] : sh[rl+2][c];
        hs[(size_t)((b << 9) + t0 + rl)*CC + c] = val + mu[c]*shv;
    }
}

// ---------------- GEMM mainloop: 8 rows x 128 cols, 128 threads ----------------
// Warp w owns rows 2w,2w+1 of the tile; lane owns 4 cols. A staged in smem
// (scalar broadcast reads), B read straight from global: the 4 warps stream
// the same W[k] row -> L1-resident (W fits L1).
template<int K>
__device__ __forceinline__ void gemm8_main(const float* __restrict__ A,
                                           const float* __restrict__ W, int ldw,
                                           int bn, float (&acc)[2][4]) {
    __shared__ float As[8*K];
    const int tid = threadIdx.x, w = tid >> 5, lane = tid & 31;
    const int bm = blockIdx.y << 3;
    constexpr int QK = K/4;
    #pragma unroll
    for (int j = tid; j < 2*K; j += 128) {
        int r = j / QK, q = j - r*QK;
        *(float4*)&As[r*K + (q << 2)] = *(const float4*)(A + (size_t)(bm + r)*K + (q << 2));
    }
    __syncthreads();
    const float* Wp = W + bn + (lane << 2);
    const float* Ar0 = &As[(w << 1)*K];
    const float* Ar1 = Ar0 + K;
    #pragma unroll 16
    for (int k = 0; k < K; k++) {
        float4 bv = *(const float4*)(Wp + (size_t)k*ldw);
        float a0 = Ar0[k], a1 = Ar1[k];
        acc[0][0] = fmaf(a0, bv.x, acc[0][0]);
        acc[0][1] = fmaf(a0, bv.y, acc[0][1]);
        acc[0][2] = fmaf(a0, bv.z, acc[0][2]);
        acc[0][3] = fmaf(a0, bv.w, acc[0][3]);
        acc[1][0] = fmaf(a1, bv.x, acc[1][0]);
        acc[1][1] = fmaf(a1, bv.y, acc[1][1]);
        acc[1][2] = fmaf(a1, bv.z, acc[1][2]);
        acc[1][3] = fmaf(a1, bv.w, acc[1][3]);
    }
}

// ---------------- fused r/k/v GEMMs (z selects matrix) ----------------
__global__ void __launch_bounds__(128)
rkv_kernel(const float* __restrict__ hs,
           const float* __restrict__ Wr, const float* __restrict__ br,
           const float* __restrict__ Wk, const float* __restrict__ bk,
           const float* __restrict__ Wv, const float* __restrict__ bv,
           float* __restrict__ ro, float* __restrict__ ko, float* __restrict__ vo) {
    const int z = blockIdx.z;
    const float* W  = (z == 0) ? Wr : (z == 1) ? Wk : Wv;
    const float* bb = (z == 0) ? br : (z == 1) ? bk : bv;
    float* o        = (z == 0) ? ro : (z == 1) ? ko : vo;
    float acc[2][4] = {};
    gemm8_main<CC>(hs, W, CC, 0, acc);
    const int w = threadIdx.x >> 5, lane = threadIdx.x & 31, bm = blockIdx.y << 3;
    float4 bias4 = *(const float4*)(bb + (lane << 2));
    #pragma unroll
    for (int i = 0; i < 2; i++) {
        int m = bm + (w << 1) + i;
        float v0 = acc[i][0] + bias4.x, v1 = acc[i][1] + bias4.y;
        float v2 = acc[i][2] + bias4.z, v3 = acc[i][3] + bias4.w;
        if (z == 0) {
            v0 = 1.0f/(1.0f + expf(-v0)); v1 = 1.0f/(1.0f + expf(-v1));
            v2 = 1.0f/(1.0f + expf(-v2)); v3 = 1.0f/(1.0f + expf(-v3));
        }
        *(float4*)(o + (size_t)m*CC + (lane << 2)) = make_float4(v0, v1, v2, v3);
    }
}

// ---------------- WKV: wk = r * x_f (x_b == x_f identity) ----------------
// 1024 threads = 32 warps. Warps 0-7: seg0 rows 0-7; 8-15: seg1; etc, so the
// 8 warps of a segment stream the same v[l] rows together (L1 multicast).
__global__ void __launch_bounds__(1024, 1)
wkv_kernel(const float* __restrict__ k, const float* __restrict__ v,
           const float* __restrict__ r, const float* __restrict__ wd,
           float* __restrict__ wk) {
    __shared__ float s_acc[4][8][CC];
    const int tid = threadIdx.x;
    const int wid = tid >> 5, lane = tid & 31;
    const int seg = wid >> 3, rloc = wid & 7;
    const int row  = (blockIdx.x << 3) + rloc;
    const int b    = row >> 9;
    const int c0   = lane << 2;

    float4 k4 = *(const float4*)(k  + (size_t)row*CC + c0);
    float4 w4 = *(const float4*)(wd + c0);
    float a0 = k4.x * (-expf(w4.x));
    float a1 = k4.y * (-expf(w4.y));
    float a2 = k4.z * (-expf(w4.z));
    float a3 = k4.w * (-expf(w4.w));
    float amax = wmax(fmaxf(fmaxf(a0, a1), fmaxf(a2, a3)));
    float b0 = a0 - amax, b1 = a1 - amax, b2 = a2 - amax, b3 = a3 - amax;

    const float inv511 = 1.0f/511.0f;
    const int l0 = seg << 7;
    const float sstart = (float)(511 - l0) * inv511;
    float E0 = expf(b0*sstart), E1 = expf(b1*sstart);
    float E2 = expf(b2*sstart), E3 = expf(b3*sstart);
    float g0 = expf(-b0*inv511), g1 = expf(-b1*inv511);
    float g2 = expf(-b2*inv511), g3 = expf(-b3*inv511);

    float acc0 = 0.f, acc1 = 0.f, acc2 = 0.f, acc3 = 0.f;
    const float* vbase = v + ((size_t)(b << 9))*CC + c0;

    #pragma unroll 4
    for (int l = l0; l < l0 + 128; ++l) {
        float z = wsum((E0 + E1) + (E2 + E3));
        float inv = rcpa(z + 1e-6f);
        float4 vv = *(const float4*)(vbase + (size_t)l*CC);
        acc0 = fmaf(E0*inv, vv.x, acc0);
        acc1 = fmaf(E1*inv, vv.y, acc1);
        acc2 = fmaf(E2*inv, vv.z, acc2);
        acc3 = fmaf(E3*inv, vv.w, acc3);
        E0 *= g0; E1 *= g1; E2 *= g2; E3 *= g3;
    }

    s_acc[seg][rloc][c0+0] = acc0;
    s_acc[seg][rloc][c0+1] = acc1;
    s_acc[seg][rloc][c0+2] = acc2;
    s_acc[seg][rloc][c0+3] = acc3;
    __syncthreads();

    const int rl = tid >> 7, c = tid & (CC-1);
    float sum = (s_acc[0][rl][c] + s_acc[1][rl][c]) + (s_acc[2][rl][c] + s_acc[3][rl][c]);
    const int grow = (blockIdx.x << 3) + rl;
    wk[(size_t)grow*CC + c] = r[(size_t)grow*CC + c] * sum;
}

// ---------------- Wo GEMM + residual + LN2 (fused) ----------------
__global__ void __launch_bounds__(128)
wo_ln_kernel(const float* __restrict__ wkin, const float* __restrict__ Wo,
             const float* __restrict__ bo, const float* __restrict__ x,
             const float* __restrict__ g2, const float* __restrict__ be2,
             float* __restrict__ y, float* __restrict__ h2) {
    float acc[2][4] = {};
    gemm8_main<CC>(wkin, Wo, CC, 0, acc);
    const int w = threadIdx.x >> 5, lane = threadIdx.x & 31, bm = blockIdx.y << 3;
    float4 bias4 = *(const float4*)(bo  + (lane << 2));
    float4 g4    = *(const float4*)(g2  + (lane << 2));
    float4 b4    = *(const float4*)(be2 + (lane << 2));
    #pragma unroll
    for (int i = 0; i < 2; i++) {
        int m = bm + (w << 1) + i;
        float4 xv = *(const float4*)(x + (size_t)m*CC + (lane << 2));
        float y0 = acc[i][0] + bias4.x + xv.x;
        float y1 = acc[i][1] + bias4.y + xv.y;
        float y2 = acc[i][2] + bias4.z + xv.z;
        float y3 = acc[i][3] + bias4.w + xv.w;
        *(float4*)(y + (size_t)m*CC + (lane << 2)) = make_float4(y0, y1, y2, y3);
        float mean = wsum((y0 + y1) + (y2 + y3)) * (1.0f/CC);
        float d0 = y0 - mean, d1 = y1 - mean, d2 = y2 - mean, d3 = y3 - mean;
        float rs = rsqrtf(wsum((d0*d0 + d1*d1) + (d2*d2 + d3*d3)) * (1.0f/CC) + 1e-5f);
        *(float4*)(h2 + (size_t)m*CC + (lane << 2)) =
            make_float4(d0*rs*g4.x + b4.x, d1*rs*g4.y + b4.y,
                        d2*rs*g4.z + b4.z, d3*rs*g4.w + b4.w);
    }
}

// ---------------- W1 GEMM + exact gelu ----------------
__global__ void __launch_bounds__(128)
w1_kernel(const float* __restrict__ h2, const float* __restrict__ W1,
          const float* __restrict__ b1, float* __restrict__ mid) {
    const int bn = blockIdx.x << 7;
    float acc[2][4] = {};
    gemm8_main<CC>(h2, W1, HH, bn, acc);
    const int w = threadIdx.x >> 5, lane = threadIdx.x & 31, bm = blockIdx.y << 3;
    float4 bias4 = *(const float4*)(b1 + bn + (lane << 2));
    #pragma unroll
    for (int i = 0; i < 2; i++) {
        int m = bm + (w << 1) + i;
        float v0 = acc[i][0] + bias4.x, v1 = acc[i][1] + bias4.y;
        float v2 = acc[i][2] + bias4.z, v3 = acc[i][3] + bias4.w;
        const float s = 0.70710678118654752f;
        v0 = 0.5f*v0*(1.0f + erff(v0*s));
        v1 = 0.5f*v1*(1.0f + erff(v1*s));
        v2 = 0.5f*v2*(1.0f + erff(v2*s));
        v3 = 0.5f*v3*(1.0f + erff(v3*s));
        *(float4*)(mid + (size_t)m*HH + bn + (lane << 2)) = make_float4(v0, v1, v2, v3);
    }
}

// ---------------- W2 GEMM + residual -> out ----------------
__global__ void __launch_bounds__(128)
w2_kernel(const float* __restrict__ mid, const float* __restrict__ W2,
          const float* __restrict__ b2, const float* __restrict__ y,
          float* __restrict__ out) {
    float acc[2][4] = {};
    gemm8_main<HH>(mid, W2, CC, 0, acc);
    const int w = threadIdx.x >> 5, lane = threadIdx.x & 31, bm = blockIdx.y << 3;
    float4 bias4 = *(const float4*)(b2 + (lane << 2));
    #pragma unroll
    for (int i = 0; i < 2; i++) {
        int m = bm + (w << 1) + i;
        float4 yv = *(const float4*)(y + (size_t)m*CC + (lane << 2));
        *(float4*)(out + (size_t)m*CC + (lane << 2)) =
            make_float4(acc[i][0] + bias4.x + yv.x, acc[i][1] + bias4.y + yv.y,
                        acc[i][2] + bias4.z + yv.z, acc[i][3] + bias4.w + yv.w);
    }
}

// ---------------- launch ----------------
extern "C" void kernel_launch(void* const* d_in, const int* in_sizes, int n_in,
                              void* d_out, int out_size) {
    const float* x       = (const float*)d_in[0];
    const float* ln1_g   = (const float*)d_in[1];
    const float* ln1_b   = (const float*)d_in[2];
    const float* mu      = (const float*)d_in[3];
    const float* Wr      = (const float*)d_in[4];
    const float* br      = (const float*)d_in[5];
    const float* Wk      = (const float*)d_in[6];
    const float* bk      = (const float*)d_in[7];
    const float* Wv      = (const float*)d_in[8];
    const float* bv      = (const float*)d_in[9];
    const float* w_decay = (const float*)d_in[10];
    const float* Wo      = (const float*)d_in[11];
    const float* bo      = (const float*)d_in[12];
    const float* ln2_g   = (const float*)d_in[13];
    const float* ln2_b   = (const float*)d_in[14];
    const float* W1      = (const float*)d_in[15];
    const float* b1      = (const float*)d_in[16];
    const float* W2      = (const float*)d_in[17];
    const float* b2      = (const float*)d_in[18];
    float* out = (float*)d_out;

    float *hs, *r_, *k_, *v_, *wkp, *y, *h2, *mid;
    cudaGetSymbolAddress((void**)&hs,  g_hs);
    cudaGetSymbolAddress((void**)&r_,  g_r);
    cudaGetSymbolAddress((void**)&k_,  g_k);
    cudaGetSymbolAddress((void**)&v_,  g_v);
    cudaGetSymbolAddress((void**)&wkp, g_wk);
    cudaGetSymbolAddress((void**)&y,   g_y);
    cudaGetSymbolAddress((void**)&h2,  g_h2);
    cudaGetSymbolAddress((void**)&mid, g_mid);

    ln_shift_kernel<<<128, 256>>>(x, ln1_g, ln1_b, mu, hs);
    rkv_kernel<<<dim3(1, 128, 3), 128>>>(hs, Wr, br, Wk, bk, Wv, bv, r_, k_, v_);
    wkv_kernel<<<128, 1024>>>(k_, v_, r_, w_decay, wkp);
    wo_ln_kernel<<<dim3(1, 128), 128>>>(wkp, Wo, bo, x, ln2_g, ln2_b, y, h2);
    w1_kernel<<<dim3(4, 128), 128>>>(h2, W1, b1, mid);
    w2_kernel<<<dim3(1, 128), 128>>>(mid, W2, b2, y, out);
}

// round 4
// speedup vs baseline: 1.9244x; 1.2787x over previous
#include <cuda_runtime.h>
#include <math.h>
#include <stdint.h>

#define TT 512
#define CC 128
#define HH 512
#define ROWS 1024   // B*T

// ---------------- scratch ----------------
__device__ float g_hs [ROWS*CC];
__device__ float g_r  [ROWS*CC];
__device__ float g_k  [ROWS*CC];
__device__ float g_v  [ROWS*CC];
__device__ float g_wk [ROWS*CC];
__device__ float g_y  [ROWS*CC];
__device__ float g_h2 [ROWS*CC];
__device__ float g_mid[ROWS*HH];

// ---------------- helpers ----------------
__device__ __forceinline__ float wsum(float x) {
    #pragma unroll
    for (int o = 16; o; o >>= 1) x += __shfl_xor_sync(0xffffffffu, x, o);
    return x;
}
__device__ __forceinline__ float rcpa(float x) {
    float r; asm("rcp.approx.f32 %0, %1;" : "=f"(r) : "f"(x)); return r;
}
// packed f32x2 (Blackwell)
typedef unsigned long long ull;
__device__ __forceinline__ ull pack2(float x, float y) {
    ull r; asm("mov.b64 %0, {%1, %2};" : "=l"(r) : "f"(x), "f"(y)); return r;
}
__device__ __forceinline__ void unpack2(ull p, float& x, float& y) {
    asm("mov.b64 {%0, %1}, %2;" : "=f"(x), "=f"(y) : "l"(p));
}
__device__ __forceinline__ ull fma2(ull a, ull b, ull c) {
    ull d; asm("fma.rn.f32x2 %0, %1, %2, %3;" : "=l"(d) : "l"(a), "l"(b), "l"(c)); return d;
}
__device__ __forceinline__ ull mul2(ull a, ull b) {
    ull d; asm("mul.rn.f32x2 %0, %1, %2;" : "=l"(d) : "l"(a), "l"(b)); return d;
}
__device__ __forceinline__ ull add2(ull a, ull b) {
    ull d; asm("add.rn.f32x2 %0, %1, %2;" : "=l"(d) : "l"(a), "l"(b)); return d;
}
// cp.async
__device__ __forceinline__ void cpasync16(uint32_t saddr, const void* g) {
    asm volatile("cp.async.ca.shared.global [%0], [%1], 16;" :: "r"(saddr), "l"(g));
}
__device__ __forceinline__ void cpcommit() { asm volatile("cp.async.commit_group;"); }
template<int N> __device__ __forceinline__ void cpwait() {
    asm volatile("cp.async.wait_group %0;" :: "n"(N));
}

// ---------------- fused LN1 + TemporalShift: 8 rows/block, grid 128 ----------------
__global__ void __launch_bounds__(256)
ln_shift_kernel(const float* __restrict__ x,
                const float* __restrict__ gam, const float* __restrict__ bet,
                const float* __restrict__ mu, float* __restrict__ hs) {
    __shared__ float sh[10][CC];
    const int tid = threadIdx.x;
    const int w = tid >> 5, lane = tid & 31;
    const int b  = blockIdx.x >> 6;
    const int t0 = (blockIdx.x & 63) << 3;

    float4 g4 = *(const float4*)(gam + (lane << 2));
    float4 b4 = *(const float4*)(bet + (lane << 2));

    for (int hr = w; hr < 10; hr += 8) {
        int t = t0 - 1 + hr;
        bool ok = (t >= 0) && (t < TT);
        float4 xv = make_float4(0.f, 0.f, 0.f, 0.f);
        if (ok) xv = *(const float4*)(x + (size_t)((b << 9) + t)*CC + (lane << 2));
        float mean = wsum((xv.x + xv.y) + (xv.z + xv.w)) * (1.0f/CC);
        float d0 = xv.x - mean, d1 = xv.y - mean, d2 = xv.z - mean, d3 = xv.w - mean;
        float rs = rsqrtf(wsum((d0*d0 + d1*d1) + (d2*d2 + d3*d3)) * (1.0f/CC) + 1e-5f);
        int c = lane << 2;
        sh[hr][c+0] = ok ? d0*rs*g4.x + b4.x : 0.f;
        sh[hr][c+1] = ok ? d1*rs*g4.y + b4.y : 0.f;
        sh[hr][c+2] = ok ? d2*rs*g4.z + b4.z : 0.f;
        sh[hr][c+3] = ok ? d3*rs*g4.w + b4.w : 0.f;
    }
    __syncthreads();
    for (int i = tid; i < 8*CC; i += 256) {
        int rl = i >> 7, c = i & (CC-1);
        float val = sh[rl+1][c];
        float shv = (c < CC/2) ? sh[rl][c] : sh[rl+2][c];
        hs[(size_t)((b << 9) + t0 + rl)*CC + c] = val + mu[c]*shv;
    }
}

// ---------------- GEMM core: 8 rows x 128 cols, 128 threads (4 warps) ----------------
// Warp w owns rows 2w,2w+1; lane owns 4 cols. B double-buffered via cp.async in
// 32-k chunks; A held in registers + shfl.idx broadcast; math in f32x2.
// acc[row][pair]: pair 0 = cols (4l,4l+1), pair 1 = cols (4l+2,4l+3).
template<int K>
__device__ __forceinline__ void gemm8_core(const float* __restrict__ A,
                                           const float* __restrict__ W, int ldw, int bn,
                                           ull (&acc)[2][2]) {
    __shared__ float Bs[2][32][CC];
    const int tid = threadIdx.x, w = tid >> 5, lane = tid & 31;
    const int bm = blockIdx.y << 3;
    const int r0 = bm + (w << 1), r1 = r0 + 1;
    constexpr int NC = K / 32;
    uint32_t sbase = (uint32_t)__cvta_generic_to_shared(&Bs[0][0][0]);

    auto stage = [&](int c, int buf) {
        const float* src = W + (size_t)(c*32)*ldw + bn;
        #pragma unroll
        for (int j = 0; j < 8; j++) {
            int idx = tid + j*128;           // float4 index, 0..1023
            int kk = idx >> 5, q = idx & 31;
            cpasync16(sbase + (uint32_t)(buf*32*CC + kk*CC + (q << 2))*4u,
                      src + (size_t)kk*ldw + (q << 2));
        }
        cpcommit();
    };
    stage(0, 0);
    float a0 = A[(size_t)r0*K + lane];
    float a1 = A[(size_t)r1*K + lane];
    for (int c = 0; c < NC; c++) {
        float an0 = 0.f, an1 = 0.f;
        if (c + 1 < NC) {
            stage(c+1, (c+1)&1);
            an0 = A[(size_t)r0*K + (c+1)*32 + lane];
            an1 = A[(size_t)r1*K + (c+1)*32 + lane];
            cpwait<1>();
        } else {
            cpwait<0>();
        }
        __syncthreads();
        const ull* bp = (const ull*)&Bs[c&1][0][lane << 2];
        #pragma unroll
        for (int j = 0; j < 32; j++) {
            ull bxy = bp[j*(CC/2)];
            ull bzw = bp[j*(CC/2) + 1];
            float s0 = __shfl_sync(0xffffffffu, a0, j);
            float s1 = __shfl_sync(0xffffffffu, a1, j);
            ull s0d = pack2(s0, s0);
            ull s1d = pack2(s1, s1);
            acc[0][0] = fma2(s0d, bxy, acc[0][0]);
            acc[0][1] = fma2(s0d, bzw, acc[0][1]);
            acc[1][0] = fma2(s1d, bxy, acc[1][0]);
            acc[1][1] = fma2(s1d, bzw, acc[1][1]);
        }
        __syncthreads();
        a0 = an0; a1 = an1;
    }
}
__device__ __forceinline__ void acc_unpack(ull (&acc)[2][2], float (&o)[2][4]) {
    #pragma unroll
    for (int i = 0; i < 2; i++) {
        unpack2(acc[i][0], o[i][0], o[i][1]);
        unpack2(acc[i][1], o[i][2], o[i][3]);
    }
}

// ---------------- fused r/k/v GEMMs (z selects matrix) ----------------
__global__ void __launch_bounds__(128)
rkv_kernel(const float* __restrict__ hs,
           const float* __restrict__ Wr, const float* __restrict__ br,
           const float* __restrict__ Wk, const float* __restrict__ bk,
           const float* __restrict__ Wv, const float* __restrict__ bv,
           float* __restrict__ ro, float* __restrict__ ko, float* __restrict__ vo) {
    const int z = blockIdx.z;
    const float* W  = (z == 0) ? Wr : (z == 1) ? Wk : Wv;
    const float* bb = (z == 0) ? br : (z == 1) ? bk : bv;
    float* o        = (z == 0) ? ro : (z == 1) ? ko : vo;
    ull acc[2][2] = {{0ull,0ull},{0ull,0ull}};
    gemm8_core<CC>(hs, W, CC, 0, acc);
    float a[2][4]; acc_unpack(acc, a);
    const int w = threadIdx.x >> 5, lane = threadIdx.x & 31, bm = blockIdx.y << 3;
    float4 bias4 = *(const float4*)(bb + (lane << 2));
    #pragma unroll
    for (int i = 0; i < 2; i++) {
        int m = bm + (w << 1) + i;
        float v0 = a[i][0] + bias4.x, v1 = a[i][1] + bias4.y;
        float v2 = a[i][2] + bias4.z, v3 = a[i][3] + bias4.w;
        if (z == 0) {
            v0 = 1.0f/(1.0f + expf(-v0)); v1 = 1.0f/(1.0f + expf(-v1));
            v2 = 1.0f/(1.0f + expf(-v2)); v3 = 1.0f/(1.0f + expf(-v3));
        }
        *(float4*)(o + (size_t)m*CC + (lane << 2)) = make_float4(v0, v1, v2, v3);
    }
}

// ---------------- WKV: wk = r * x_f (x_b == x_f identity) ----------------
// 1024 thr = 32 warps = 8 rows x 4 segs. Within a warp: lane = 16h + p;
// lane owns 8 channels (c = 8p..8p+7); half h processes l = l0 + 2i + h.
// Reduction over 16 lanes (4 butterfly levels); E/acc math packed f32x2.
__global__ void __launch_bounds__(1024, 1)
wkv_kernel(const float* __restrict__ k, const float* __restrict__ v,
           const float* __restrict__ r, const float* __restrict__ wd,
           float* __restrict__ wk) {
    __shared__ float s_acc[4][8][CC];
    const int tid = threadIdx.x;
    const int wid = tid >> 5, lane = tid & 31;
    const int seg = wid >> 3, rloc = wid & 7;
    const int row = (blockIdx.x << 3) + rloc;
    const int bb  = row >> 9;
    const int h = lane >> 4, p = lane & 15;
    const int c0 = p << 3;

    float bv8[8];
    {
        float4 k0 = *(const float4*)(k  + (size_t)row*CC + c0);
        float4 k1 = *(const float4*)(k  + (size_t)row*CC + c0 + 4);
        float4 w0 = *(const float4*)(wd + c0);
        float4 w1 = *(const float4*)(wd + c0 + 4);
        bv8[0] = k0.x * (-expf(w0.x)); bv8[1] = k0.y * (-expf(w0.y));
        bv8[2] = k0.z * (-expf(w0.z)); bv8[3] = k0.w * (-expf(w0.w));
        bv8[4] = k1.x * (-expf(w1.x)); bv8[5] = k1.y * (-expf(w1.y));
        bv8[6] = k1.z * (-expf(w1.z)); bv8[7] = k1.w * (-expf(w1.w));
    }
    float amax = bv8[0];
    #pragma unroll
    for (int i = 1; i < 8; i++) amax = fmaxf(amax, bv8[i]);
    #pragma unroll
    for (int o = 16; o; o >>= 1) amax = fmaxf(amax, __shfl_xor_sync(0xffffffffu, amax, o));
    #pragma unroll
    for (int i = 0; i < 8; i++) bv8[i] -= amax;

    const float inv511 = 1.0f/511.0f;
    const int l0 = seg << 7;
    const float s0 = (float)(511 - (l0 + h)) * inv511;
    ull E2[4], g2[4];
    #pragma unroll
    for (int j = 0; j < 4; j++) {
        E2[j] = pack2(expf(bv8[2*j]*s0),          expf(bv8[2*j+1]*s0));
        g2[j] = pack2(expf(-2.0f*bv8[2*j]*inv511), expf(-2.0f*bv8[2*j+1]*inv511));
    }
    ull acc2[4] = {0ull, 0ull, 0ull, 0ull};
    const float* vp = v + ((size_t)(bb << 9) + l0 + h)*CC + c0;

    #pragma unroll 4
    for (int i = 0; i < 64; i++) {
        ull t = add2(add2(E2[0], E2[1]), add2(E2[2], E2[3]));
        float zl, zh; unpack2(t, zl, zh);
        float z = zl + zh;
        #pragma unroll
        for (int o = 8; o; o >>= 1) z += __shfl_xor_sync(0xffffffffu, z, o);
        float inv = rcpa(z + 1e-6f);
        ull invd = pack2(inv, inv);
        ulonglong2 v01 = *(const ulonglong2*)(vp);
        ulonglong2 v23 = *(const ulonglong2*)(vp + 4);
        acc2[0] = fma2(mul2(E2[0], invd), v01.x, acc2[0]);
        acc2[1] = fma2(mul2(E2[1], invd), v01.y, acc2[1]);
        acc2[2] = fma2(mul2(E2[2], invd), v23.x, acc2[2]);
        acc2[3] = fma2(mul2(E2[3], invd), v23.y, acc2[3]);
        E2[0] = mul2(E2[0], g2[0]); E2[1] = mul2(E2[1], g2[1]);
        E2[2] = mul2(E2[2], g2[2]); E2[3] = mul2(E2[3], g2[3]);
        vp += 2*CC;
    }

    // combine even/odd-l halves, write per-seg partials
    #pragma unroll
    for (int j = 0; j < 4; j++) {
        float x, y; unpack2(acc2[j], x, y);
        x += __shfl_xor_sync(0xffffffffu, x, 16);
        y += __shfl_xor_sync(0xffffffffu, y, 16);
        if (h == 0) {
            s_acc[seg][rloc][c0 + 2*j    ] = x;
            s_acc[seg][rloc][c0 + 2*j + 1] = y;
        }
    }
    __syncthreads();

    const int rl = tid >> 7, c = tid & (CC-1);
    float sum = (s_acc[0][rl][c] + s_acc[1][rl][c]) + (s_acc[2][rl][c] + s_acc[3][rl][c]);
    const int grow = (blockIdx.x << 3) + rl;
    wk[(size_t)grow*CC + c] = r[(size_t)grow*CC + c] * sum;
}

// ---------------- Wo GEMM + residual + LN2 (fused) ----------------
__global__ void __launch_bounds__(128)
wo_ln_kernel(const float* __restrict__ wkin, const float* __restrict__ Wo,
             const float* __restrict__ bo, const float* __restrict__ x,
             const float* __restrict__ g2, const float* __restrict__ be2,
             float* __restrict__ y, float* __restrict__ h2) {
    ull acc[2][2] = {{0ull,0ull},{0ull,0ull}};
    gemm8_core<CC>(wkin, Wo, CC, 0, acc);
    float a[2][4]; acc_unpack(acc, a);
    const int w = threadIdx.x >> 5, lane = threadIdx.x & 31, bm = blockIdx.y << 3;
    float4 bias4 = *(const float4*)(bo  + (lane << 2));
    float4 g4    = *(const float4*)(g2  + (lane << 2));
    float4 b4    = *(const float4*)(be2 + (lane << 2));
    #pragma unroll
    for (int i = 0; i < 2; i++) {
        int m = bm + (w << 1) + i;
        float4 xv = *(const float4*)(x + (size_t)m*CC + (lane << 2));
        float y0 = a[i][0] + bias4.x + xv.x;
        float y1 = a[i][1] + bias4.y + xv.y;
        float y2 = a[i][2] + bias4.z + xv.z;
        float y3 = a[i][3] + bias4.w + xv.w;
        *(float4*)(y + (size_t)m*CC + (lane << 2)) = make_float4(y0, y1, y2, y3);
        float mean = wsum((y0 + y1) + (y2 + y3)) * (1.0f/CC);
        float d0 = y0 - mean, d1 = y1 - mean, d2 = y2 - mean, d3 = y3 - mean;
        float rs = rsqrtf(wsum((d0*d0 + d1*d1) + (d2*d2 + d3*d3)) * (1.0f/CC) + 1e-5f);
        *(float4*)(h2 + (size_t)m*CC + (lane << 2)) =
            make_float4(d0*rs*g4.x + b4.x, d1*rs*g4.y + b4.y,
                        d2*rs*g4.z + b4.z, d3*rs*g4.w + b4.w);
    }
}

// ---------------- W1 GEMM + exact gelu ----------------
__global__ void __launch_bounds__(128)
w1_kernel(const float* __restrict__ h2, const float* __restrict__ W1,
          const float* __restrict__ b1, float* __restrict__ mid) {
    const int bn = blockIdx.x << 7;
    ull acc[2][2] = {{0ull,0ull},{0ull,0ull}};
    gemm8_core<CC>(h2, W1, HH, bn, acc);
    float a[2][4]; acc_unpack(acc, a);
    const int w = threadIdx.x >> 5, lane = threadIdx.x & 31, bm = blockIdx.y << 3;
    float4 bias4 = *(const float4*)(b1 + bn + (lane << 2));
    #pragma unroll
    for (int i = 0; i < 2; i++) {
        int m = bm + (w << 1) + i;
        float v0 = a[i][0] + bias4.x, v1 = a[i][1] + bias4.y;
        float v2 = a[i][2] + bias4.z, v3 = a[i][3] + bias4.w;
        const float s = 0.70710678118654752f;
        v0 = 0.5f*v0*(1.0f + erff(v0*s));
        v1 = 0.5f*v1*(1.0f + erff(v1*s));
        v2 = 0.5f*v2*(1.0f + erff(v2*s));
        v3 = 0.5f*v3*(1.0f + erff(v3*s));
        *(float4*)(mid + (size_t)m*HH + bn + (lane << 2)) = make_float4(v0, v1, v2, v3);
    }
}

// ---------------- W2 GEMM + residual -> out ----------------
__global__ void __launch_bounds__(128)
w2_kernel(const float* __restrict__ mid, const float* __restrict__ W2,
          const float* __restrict__ b2, const float* __restrict__ y,
          float* __restrict__ out) {
    ull acc[2][2] = {{0ull,0ull},{0ull,0ull}};
    gemm8_core<HH>(mid, W2, CC, 0, acc);
    float a[2][4]; acc_unpack(acc, a);
    const int w = threadIdx.x >> 5, lane = threadIdx.x & 31, bm = blockIdx.y << 3;
    float4 bias4 = *(const float4*)(b2 + (lane << 2));
    #pragma unroll
    for (int i = 0; i < 2; i++) {
        int m = bm + (w << 1) + i;
        float4 yv = *(const float4*)(y + (size_t)m*CC + (lane << 2));
        *(float4*)(out + (size_t)m*CC + (lane << 2)) =
            make_float4(a[i][0] + bias4.x + yv.x, a[i][1] + bias4.y + yv.y,
                        a[i][2] + bias4.z + yv.z, a[i][3] + bias4.w + yv.w);
    }
}

// ---------------- launch ----------------
extern "C" void kernel_launch(void* const* d_in, const int* in_sizes, int n_in,
                              void* d_out, int out_size) {
    const float* x       = (const float*)d_in[0];
    const float* ln1_g   = (const float*)d_in[1];
    const float* ln1_b   = (const float*)d_in[2];
    const float* mu      = (const float*)d_in[3];
    const float* Wr      = (const float*)d_in[4];
    const float* br      = (const float*)d_in[5];
    const float* Wk      = (const float*)d_in[6];
    const float* bk      = (const float*)d_in[7];
    const float* Wv      = (const float*)d_in[8];
    const float* bv      = (const float*)d_in[9];
    const float* w_decay = (const float*)d_in[10];
    const float* Wo      = (const float*)d_in[11];
    const float* bo      = (const float*)d_in[12];
    const float* ln2_g   = (const float*)d_in[13];
    const float* ln2_b   = (const float*)d_in[14];
    const float* W1      = (const float*)d_in[15];
    const float* b1      = (const float*)d_in[16];
    const float* W2      = (const float*)d_in[17];
    const float* b2      = (const float*)d_in[18];
    float* out = (float*)d_out;

    float *hs, *r_, *k_, *v_, *wkp, *y, *h2, *mid;
    cudaGetSymbolAddress((void**)&hs,  g_hs);
    cudaGetSymbolAddress((void**)&r_,  g_r);
    cudaGetSymbolAddress((void**)&k_,  g_k);
    cudaGetSymbolAddress((void**)&v_,  g_v);
    cudaGetSymbolAddress((void**)&wkp, g_wk);
    cudaGetSymbolAddress((void**)&y,   g_y);
    cudaGetSymbolAddress((void**)&h2,  g_h2);
    cudaGetSymbolAddress((void**)&mid, g_mid);

    ln_shift_kernel<<<128, 256>>>(x, ln1_g, ln1_b, mu, hs);
    rkv_kernel<<<dim3(1, 128, 3), 128>>>(hs, Wr, br, Wk, bk, Wv, bv, r_, k_, v_);
    wkv_kernel<<<128, 1024>>>(k_, v_, r_, w_decay, wkp);
    wo_ln_kernel<<<dim3(1, 128), 128>>>(wkp, Wo, bo, x, ln2_g, ln2_b, y, h2);
    w1_kernel<<<dim3(4, 128), 128>>>(h2, W1, b1, mid);
    w2_kernel<<<dim3(1, 128), 128>>>(mid, W2, b2, y, out);
}

// round 5
// speedup vs baseline: 2.0173x; 1.0483x over previous
#include <cuda_runtime.h>
#include <math.h>
#include <stdint.h>

#define TT 512
#define CC 128
#define HH 512
#define ROWS 1024   // B*T
#define CHUNK 32    // k-chunk for GEMM staging

// ---------------- scratch ----------------
__device__ float g_hs [ROWS*CC];
__device__ float g_r  [ROWS*CC];
__device__ float g_k  [ROWS*CC];
__device__ float g_v  [ROWS*CC];
__device__ float g_wk [ROWS*CC];
__device__ float g_y  [ROWS*CC];
__device__ float g_h2 [ROWS*CC];
__device__ float g_mid[ROWS*HH];

// ---------------- helpers ----------------
__device__ __forceinline__ float wsum(float x) {
    #pragma unroll
    for (int o = 16; o; o >>= 1) x += __shfl_xor_sync(0xffffffffu, x, o);
    return x;
}
__device__ __forceinline__ float rcpa(float x) {
    float r; asm("rcp.approx.f32 %0, %1;" : "=f"(r) : "f"(x)); return r;
}
typedef unsigned long long ull;
__device__ __forceinline__ ull pack2(float x, float y) {
    ull r; asm("mov.b64 %0, {%1, %2};" : "=l"(r) : "f"(x), "f"(y)); return r;
}
__device__ __forceinline__ void unpack2(ull p, float& x, float& y) {
    asm("mov.b64 {%0, %1}, %2;" : "=f"(x), "=f"(y) : "l"(p));
}
__device__ __forceinline__ ull fma2(ull a, ull b, ull c) {
    ull d; asm("fma.rn.f32x2 %0, %1, %2, %3;" : "=l"(d) : "l"(a), "l"(b), "l"(c)); return d;
}
__device__ __forceinline__ ull mul2(ull a, ull b) {
    ull d; asm("mul.rn.f32x2 %0, %1, %2;" : "=l"(d) : "l"(a), "l"(b)); return d;
}
__device__ __forceinline__ ull add2(ull a, ull b) {
    ull d; asm("add.rn.f32x2 %0, %1, %2;" : "=l"(d) : "l"(a), "l"(b)); return d;
}
__device__ __forceinline__ void cpasync16(uint32_t saddr, const void* g) {
    asm volatile("cp.async.ca.shared.global [%0], [%1], 16;" :: "r"(saddr), "l"(g));
}
__device__ __forceinline__ void cpcommit() { asm volatile("cp.async.commit_group;"); }
template<int N> __device__ __forceinline__ void cpwait() {
    asm volatile("cp.async.wait_group %0;" :: "n"(N));
}

// ---------------- fused LN1 + TemporalShift: 8 rows/block, grid 128 ----------------
__global__ void __launch_bounds__(256)
ln_shift_kernel(const float* __restrict__ x,
                const float* __restrict__ gam, const float* __restrict__ bet,
                const float* __restrict__ mu, float* __restrict__ hs) {
    __shared__ float sh[10][CC];
    const int tid = threadIdx.x;
    const int w = tid >> 5, lane = tid & 31;
    const int b  = blockIdx.x >> 6;
    const int t0 = (blockIdx.x & 63) << 3;

    float4 g4 = *(const float4*)(gam + (lane << 2));
    float4 b4 = *(const float4*)(bet + (lane << 2));

    for (int hr = w; hr < 10; hr += 8) {
        int t = t0 - 1 + hr;
        bool ok = (t >= 0) && (t < TT);
        float4 xv = make_float4(0.f, 0.f, 0.f, 0.f);
        if (ok) xv = *(const float4*)(x + (size_t)((b << 9) + t)*CC + (lane << 2));
        float mean = wsum((xv.x + xv.y) + (xv.z + xv.w)) * (1.0f/CC);
        float d0 = xv.x - mean, d1 = xv.y - mean, d2 = xv.z - mean, d3 = xv.w - mean;
        float rs = rsqrtf(wsum((d0*d0 + d1*d1) + (d2*d2 + d3*d3)) * (1.0f/CC) + 1e-5f);
        int c = lane << 2;
        sh[hr][c+0] = ok ? d0*rs*g4.x + b4.x : 0.f;
        sh[hr][c+1] = ok ? d1*rs*g4.y + b4.y : 0.f;
        sh[hr][c+2] = ok ? d2*rs*g4.z + b4.z : 0.f;
        sh[hr][c+3] = ok ? d3*rs*g4.w + b4.w : 0.f;
    }
    __syncthreads();
    for (int i = tid; i < 8*CC; i += 256) {
        int rl = i >> 7, c = i & (CC-1);
        float val = sh[rl+1][c];
        float shv = (c < CC/2) ? sh[rl][c] : sh[rl+2][c];
        hs[(size_t)((b << 9) + t0 + rl)*CC + c] = val + mu[c]*shv;
    }
}

// ---------------- GEMM v2 core: 8 rows x 128 cols, 256 thr, 8-way split-K ----
// Warp w computes the FULL 8x128 tile over k-slice w of each 32-k chunk (4 k).
// A staged as pre-duplicated f32x2 pairs; B double-buffered via cp.async.
// Split-K partials reduced through smem (aliases the B buffer).
struct __align__(16) SmemGemm {
    float Bs[2][CHUNK][CC];      // 32 KB
    ull   AsD[2][CHUNK][8];      //  4 KB
};

template<int K>
__device__ __forceinline__ void gemm_v2(const float* __restrict__ A, int lda,
                                        const float* __restrict__ W, int ldw, int bn,
                                        float (&outv)[4]) {
    __shared__ SmemGemm sg;
    const int tid = threadIdx.x, w = tid >> 5, lane = tid & 31;
    const int bm = blockIdx.y << 3;
    constexpr int NC = K / CHUNK;
    uint32_t bs_base = (uint32_t)__cvta_generic_to_shared(&sg.Bs[0][0][0]);

    const int ak = tid >> 3, ar = tid & 7;     // one (k, r) pair per thread per chunk

    // stage B chunk c into buffer buf
    #define STAGE_B(c, buf) do {                                                 \
        const float* _src = W + (size_t)((c)*CHUNK)*ldw + bn;                    \
        _Pragma("unroll")                                                        \
        for (int _j = 0; _j < 4; _j++) {                                         \
            int _idx = tid + _j*256;                                             \
            int _kk = _idx >> 5, _q = _idx & 31;                                 \
            cpasync16(bs_base + (uint32_t)(((buf)*CHUNK + _kk)*CC + (_q<<2))*4u, \
                      _src + (size_t)_kk*ldw + (_q<<2));                         \
        }                                                                        \
        cpcommit();                                                              \
    } while (0)

    STAGE_B(0, 0);
    float aCur = A[(size_t)(bm + ar)*lda + ak];
    sg.AsD[0][ak][ar] = pack2(aCur, aCur);

    ull acc[8][2];
    #pragma unroll
    for (int r = 0; r < 8; r++) { acc[r][0] = 0ull; acc[r][1] = 0ull; }

    #pragma unroll 1
    for (int c = 0; c < NC; c++) {
        float aNext = 0.f;
        if (c + 1 < NC) {
            STAGE_B(c+1, (c+1)&1);
            aNext = A[(size_t)(bm + ar)*lda + (c+1)*CHUNK + ak];
            cpwait<1>();
        } else {
            cpwait<0>();
        }
        __syncthreads();   // staged A+B visible; prior compute done everywhere
        const int buf = c & 1;
        #pragma unroll
        for (int j = 0; j < CHUNK/8; j++) {
            const int kk = w*(CHUNK/8) + j;
            const ull* ad = &sg.AsD[buf][kk][0];
            ulonglong2 a01 = *(const ulonglong2*)(ad);
            ulonglong2 a23 = *(const ulonglong2*)(ad + 2);
            ulonglong2 a45 = *(const ulonglong2*)(ad + 4);
            ulonglong2 a67 = *(const ulonglong2*)(ad + 6);
            ulonglong2 b   = *(const ulonglong2*)&sg.Bs[buf][kk][lane << 2];
            acc[0][0]=fma2(a01.x,b.x,acc[0][0]); acc[0][1]=fma2(a01.x,b.y,acc[0][1]);
            acc[1][0]=fma2(a01.y,b.x,acc[1][0]); acc[1][1]=fma2(a01.y,b.y,acc[1][1]);
            acc[2][0]=fma2(a23.x,b.x,acc[2][0]); acc[2][1]=fma2(a23.x,b.y,acc[2][1]);
            acc[3][0]=fma2(a23.y,b.x,acc[3][0]); acc[3][1]=fma2(a23.y,b.y,acc[3][1]);
            acc[4][0]=fma2(a45.x,b.x,acc[4][0]); acc[4][1]=fma2(a45.x,b.y,acc[4][1]);
            acc[5][0]=fma2(a45.y,b.x,acc[5][0]); acc[5][1]=fma2(a45.y,b.y,acc[5][1]);
            acc[6][0]=fma2(a67.x,b.x,acc[6][0]); acc[6][1]=fma2(a67.x,b.y,acc[6][1]);
            acc[7][0]=fma2(a67.y,b.x,acc[7][0]); acc[7][1]=fma2(a67.y,b.y,acc[7][1]);
        }
        if (c + 1 < NC) sg.AsD[(c+1)&1][ak][ar] = pack2(aNext, aNext);
        __syncthreads();   // protect buffers before next stage overwrites
    }
    #undef STAGE_B

    // split-K reduce through smem (aliases Bs: exactly 32 KB)
    float* Red = (float*)&sg.Bs[0][0][0];   // [8 warps][8 rows][128 cols]
    #pragma unroll
    for (int r = 0; r < 8; r++) {
        float x0, x1, x2, x3;
        unpack2(acc[r][0], x0, x1);
        unpack2(acc[r][1], x2, x3);
        *(float4*)&Red[((w << 3) + r)*CC + (lane << 2)] = make_float4(x0, x1, x2, x3);
    }
    __syncthreads();
    const int rr = tid >> 5, c4 = (tid & 31) << 2;
    float4 s = *(float4*)&Red[(rr)*CC + c4];
    #pragma unroll
    for (int j = 1; j < 8; j++) {
        float4 t = *(float4*)&Red[((j << 3) + rr)*CC + c4];
        s.x += t.x; s.y += t.y; s.z += t.z; s.w += t.w;
    }
    outv[0] = s.x; outv[1] = s.y; outv[2] = s.z; outv[3] = s.w;
}

// ---------------- fused r/k/v GEMMs (z selects matrix) ----------------
__global__ void __launch_bounds__(256, 1)
rkv_kernel(const float* __restrict__ hs,
           const float* __restrict__ Wr, const float* __restrict__ br,
           const float* __restrict__ Wk, const float* __restrict__ bk,
           const float* __restrict__ Wv, const float* __restrict__ bv,
           float* __restrict__ ro, float* __restrict__ ko, float* __restrict__ vo) {
    const int z = blockIdx.z;
    const float* W  = (z == 0) ? Wr : (z == 1) ? Wk : Wv;
    const float* bb = (z == 0) ? br : (z == 1) ? bk : bv;
    float* o        = (z == 0) ? ro : (z == 1) ? ko : vo;
    float ov[4];
    gemm_v2<CC>(hs, CC, W, CC, 0, ov);
    const int r = threadIdx.x >> 5, lane = threadIdx.x & 31;
    const int m = (blockIdx.y << 3) + r;
    float4 bias4 = *(const float4*)(bb + (lane << 2));
    float v0 = ov[0] + bias4.x, v1 = ov[1] + bias4.y;
    float v2 = ov[2] + bias4.z, v3 = ov[3] + bias4.w;
    if (z == 0) {
        v0 = 1.0f/(1.0f + expf(-v0)); v1 = 1.0f/(1.0f + expf(-v1));
        v2 = 1.0f/(1.0f + expf(-v2)); v3 = 1.0f/(1.0f + expf(-v3));
    }
    *(float4*)(o + (size_t)m*CC + (lane << 2)) = make_float4(v0, v1, v2, v3);
}

// ---------------- WKV: wk = r * x_f (x_b == x_f identity) ----------------
__global__ void __launch_bounds__(1024, 1)
wkv_kernel(const float* __restrict__ k, const float* __restrict__ v,
           const float* __restrict__ r, const float* __restrict__ wd,
           float* __restrict__ wk) {
    __shared__ float s_acc[4][8][CC];
    const int tid = threadIdx.x;
    const int wid = tid >> 5, lane = tid & 31;
    const int seg = wid >> 3, rloc = wid & 7;
    const int row = (blockIdx.x << 3) + rloc;
    const int bb  = row >> 9;
    const int h = lane >> 4, p = lane & 15;
    const int c0 = p << 3;

    float bv8[8];
    {
        float4 k0 = *(const float4*)(k  + (size_t)row*CC + c0);
        float4 k1 = *(const float4*)(k  + (size_t)row*CC + c0 + 4);
        float4 w0 = *(const float4*)(wd + c0);
        float4 w1 = *(const float4*)(wd + c0 + 4);
        bv8[0] = k0.x * (-expf(w0.x)); bv8[1] = k0.y * (-expf(w0.y));
        bv8[2] = k0.z * (-expf(w0.z)); bv8[3] = k0.w * (-expf(w0.w));
        bv8[4] = k1.x * (-expf(w1.x)); bv8[5] = k1.y * (-expf(w1.y));
        bv8[6] = k1.z * (-expf(w1.z)); bv8[7] = k1.w * (-expf(w1.w));
    }
    float amax = bv8[0];
    #pragma unroll
    for (int i = 1; i < 8; i++) amax = fmaxf(amax, bv8[i]);
    #pragma unroll
    for (int o = 16; o; o >>= 1) amax = fmaxf(amax, __shfl_xor_sync(0xffffffffu, amax, o));
    #pragma unroll
    for (int i = 0; i < 8; i++) bv8[i] -= amax;

    const float inv511 = 1.0f/511.0f;
    const int l0 = seg << 7;
    const float s0 = (float)(511 - (l0 + h)) * inv511;
    ull E2[4], g2[4];
    #pragma unroll
    for (int j = 0; j < 4; j++) {
        E2[j] = pack2(expf(bv8[2*j]*s0),           expf(bv8[2*j+1]*s0));
        g2[j] = pack2(expf(-2.0f*bv8[2*j]*inv511), expf(-2.0f*bv8[2*j+1]*inv511));
    }
    ull acc2[4] = {0ull, 0ull, 0ull, 0ull};
    const float* vp = v + ((size_t)(bb << 9) + l0 + h)*CC + c0;

    #pragma unroll 4
    for (int i = 0; i < 64; i++) {
        ull t = add2(add2(E2[0], E2[1]), add2(E2[2], E2[3]));
        float zl, zh; unpack2(t, zl, zh);
        float z = zl + zh;
        #pragma unroll
        for (int o = 8; o; o >>= 1) z += __shfl_xor_sync(0xffffffffu, z, o);
        float inv = rcpa(z + 1e-6f);
        ull invd = pack2(inv, inv);
        ulonglong2 v01 = *(const ulonglong2*)(vp);
        ulonglong2 v23 = *(const ulonglong2*)(vp + 4);
        acc2[0] = fma2(mul2(E2[0], invd), v01.x, acc2[0]);
        acc2[1] = fma2(mul2(E2[1], invd), v01.y, acc2[1]);
        acc2[2] = fma2(mul2(E2[2], invd), v23.x, acc2[2]);
        acc2[3] = fma2(mul2(E2[3], invd), v23.y, acc2[3]);
        E2[0] = mul2(E2[0], g2[0]); E2[1] = mul2(E2[1], g2[1]);
        E2[2] = mul2(E2[2], g2[2]); E2[3] = mul2(E2[3], g2[3]);
        vp += 2*CC;
    }

    #pragma unroll
    for (int j = 0; j < 4; j++) {
        float x, y; unpack2(acc2[j], x, y);
        x += __shfl_xor_sync(0xffffffffu, x, 16);
        y += __shfl_xor_sync(0xffffffffu, y, 16);
        if (h == 0) {
            s_acc[seg][rloc][c0 + 2*j    ] = x;
            s_acc[seg][rloc][c0 + 2*j + 1] = y;
        }
    }
    __syncthreads();

    const int rl = tid >> 7, c = tid & (CC-1);
    float sum = (s_acc[0][rl][c] + s_acc[1][rl][c]) + (s_acc[2][rl][c] + s_acc[3][rl][c]);
    const int grow = (blockIdx.x << 3) + rl;
    wk[(size_t)grow*CC + c] = r[(size_t)grow*CC + c] * sum;
}

// ---------------- Wo GEMM + residual + LN2 (fused) ----------------
__global__ void __launch_bounds__(256, 1)
wo_ln_kernel(const float* __restrict__ wkin, const float* __restrict__ Wo,
             const float* __restrict__ bo, const float* __restrict__ x,
             const float* __restrict__ g2, const float* __restrict__ be2,
             float* __restrict__ y, float* __restrict__ h2) {
    float ov[4];
    gemm_v2<CC>(wkin, CC, Wo, CC, 0, ov);
    const int r = threadIdx.x >> 5, lane = threadIdx.x & 31;
    const int m = (blockIdx.y << 3) + r;
    float4 bias4 = *(const float4*)(bo  + (lane << 2));
    float4 g4    = *(const float4*)(g2  + (lane << 2));
    float4 b4    = *(const float4*)(be2 + (lane << 2));
    float4 xv = *(const float4*)(x + (size_t)m*CC + (lane << 2));
    float y0 = ov[0] + bias4.x + xv.x;
    float y1 = ov[1] + bias4.y + xv.y;
    float y2 = ov[2] + bias4.z + xv.z;
    float y3 = ov[3] + bias4.w + xv.w;
    *(float4*)(y + (size_t)m*CC + (lane << 2)) = make_float4(y0, y1, y2, y3);
    float mean = wsum((y0 + y1) + (y2 + y3)) * (1.0f/CC);
    float d0 = y0 - mean, d1 = y1 - mean, d2 = y2 - mean, d3 = y3 - mean;
    float rs = rsqrtf(wsum((d0*d0 + d1*d1) + (d2*d2 + d3*d3)) * (1.0f/CC) + 1e-5f);
    *(float4*)(h2 + (size_t)m*CC + (lane << 2)) =
        make_float4(d0*rs*g4.x + b4.x, d1*rs*g4.y + b4.y,
                    d2*rs*g4.z + b4.z, d3*rs*g4.w + b4.w);
}

// ---------------- W1 GEMM + exact gelu ----------------
__global__ void __launch_bounds__(256, 1)
w1_kernel(const float* __restrict__ h2, const float* __restrict__ W1,
          const float* __restrict__ b1, float* __restrict__ mid) {
    const int bn = blockIdx.x << 7;
    float ov[4];
    gemm_v2<CC>(h2, CC, W1, HH, bn, ov);
    const int r = threadIdx.x >> 5, lane = threadIdx.x & 31;
    const int m = (blockIdx.y << 3) + r;
    float4 bias4 = *(const float4*)(b1 + bn + (lane << 2));
    float v0 = ov[0] + bias4.x, v1 = ov[1] + bias4.y;
    float v2 = ov[2] + bias4.z, v3 = ov[3] + bias4.w;
    const float s = 0.70710678118654752f;
    v0 = 0.5f*v0*(1.0f + erff(v0*s));
    v1 = 0.5f*v1*(1.0f + erff(v1*s));
    v2 = 0.5f*v2*(1.0f + erff(v2*s));
    v3 = 0.5f*v3*(1.0f + erff(v3*s));
    *(float4*)(mid + (size_t)m*HH + bn + (lane << 2)) = make_float4(v0, v1, v2, v3);
}

// ---------------- W2 GEMM + residual -> out ----------------
__global__ void __launch_bounds__(256, 1)
w2_kernel(const float* __restrict__ mid, const float* __restrict__ W2,
          const float* __restrict__ b2, const float* __restrict__ y,
          float* __restrict__ out) {
    float ov[4];
    gemm_v2<HH>(mid, HH, W2, CC, 0, ov);
    const int r = threadIdx.x >> 5, lane = threadIdx.x & 31;
    const int m = (blockIdx.y << 3) + r;
    float4 bias4 = *(const float4*)(b2 + (lane << 2));
    float4 yv = *(const float4*)(y + (size_t)m*CC + (lane << 2));
    *(float4*)(out + (size_t)m*CC + (lane << 2)) =
        make_float4(ov[0] + bias4.x + yv.x, ov[1] + bias4.y + yv.y,
                    ov[2] + bias4.z + yv.z, ov[3] + bias4.w + yv.w);
}

// ---------------- launch ----------------
extern "C" void kernel_launch(void* const* d_in, const int* in_sizes, int n_in,
                              void* d_out, int out_size) {
    const float* x       = (const float*)d_in[0];
    const float* ln1_g   = (const float*)d_in[1];
    const float* ln1_b   = (const float*)d_in[2];
    const float* mu      = (const float*)d_in[3];
    const float* Wr      = (const float*)d_in[4];
    const float* br      = (const float*)d_in[5];
    const float* Wk      = (const float*)d_in[6];
    const float* bk      = (const float*)d_in[7];
    const float* Wv      = (const float*)d_in[8];
    const float* bv      = (const float*)d_in[9];
    const float* w_decay = (const float*)d_in[10];
    const float* Wo      = (const float*)d_in[11];
    const float* bo      = (const float*)d_in[12];
    const float* ln2_g   = (const float*)d_in[13];
    const float* ln2_b   = (const float*)d_in[14];
    const float* W1      = (const float*)d_in[15];
    const float* b1      = (const float*)d_in[16];
    const float* W2      = (const float*)d_in[17];
    const float* b2      = (const float*)d_in[18];
    float* out = (float*)d_out;

    float *hs, *r_, *k_, *v_, *wkp, *y, *h2, *mid;
    cudaGetSymbolAddress((void**)&hs,  g_hs);
    cudaGetSymbolAddress((void**)&r_,  g_r);
    cudaGetSymbolAddress((void**)&k_,  g_k);
    cudaGetSymbolAddress((void**)&v_,  g_v);
    cudaGetSymbolAddress((void**)&wkp, g_wk);
    cudaGetSymbolAddress((void**)&y,   g_y);
    cudaGetSymbolAddress((void**)&h2,  g_h2);
    cudaGetSymbolAddress((void**)&mid, g_mid);

    ln_shift_kernel<<<128, 256>>>(x, ln1_g, ln1_b, mu, hs);
    rkv_kernel<<<dim3(1, 128, 3), 256>>>(hs, Wr, br, Wk, bk, Wv, bv, r_, k_, v_);
    wkv_kernel<<<128, 1024>>>(k_, v_, r_, w_decay, wkp);
    wo_ln_kernel<<<dim3(1, 128), 256>>>(wkp, Wo, bo, x, ln2_g, ln2_b, y, h2);
    w1_kernel<<<dim3(4, 128), 256>>>(h2, W1, b1, mid);
    w2_kernel<<<dim3(1, 128), 256>>>(mid, W2, b2, y, out);
}